// round 1
// baseline (speedup 1.0000x reference)
#include <cuda_runtime.h>
#include <math.h>

// Problem constants
#define BB   2
#define SQ   1024
#define DD   2048
#define NH   32
#define NKV  8
#define HD   64
#define FF   5632
#define ROWS (BB*SQ)   // 2048

// Scratch (device globals: allocation-free)
__device__ float g_h   [ROWS*DD];
__device__ float g_q   [ROWS*NH*HD];
__device__ float g_k   [ROWS*NKV*HD];
__device__ float g_v   [ROWS*NKV*HD];
__device__ float g_attn[ROWS*NH*HD];
__device__ float g_x2  [ROWS*DD];
__device__ float g_h2  [ROWS*DD];
__device__ float g_f1  [ROWS*FF];
__device__ float g_f2  [ROWS*FF];

// ---------------- RMSNorm: one block per row ----------------
__global__ void rmsnorm_k(const float* __restrict__ x, const float* __restrict__ w,
                          float* __restrict__ out)
{
    int row = blockIdx.x;
    const float* xr = x + (size_t)row*DD;
    float* orow = out + (size_t)row*DD;
    float ss = 0.f;
    for (int i = threadIdx.x; i < DD; i += 256) { float v = xr[i]; ss += v*v; }
    __shared__ float red[256];
    red[threadIdx.x] = ss; __syncthreads();
    for (int s = 128; s > 0; s >>= 1) {
        if (threadIdx.x < s) red[threadIdx.x] += red[threadIdx.x+s];
        __syncthreads();
    }
    float inv = rsqrtf(red[0]/(float)DD + 1e-5f);
    for (int i = threadIdx.x; i < DD; i += 256) orow[i] = xr[i]*inv*w[i];
}

// ---------------- RoPE (in place) ----------------
__global__ void rope_k(float* __restrict__ t, const float* __restrict__ cs,
                       const float* __restrict__ sn, int nheads, int total)
{
    for (int idx = blockIdx.x*blockDim.x + threadIdx.x; idx < total;
         idx += gridDim.x*blockDim.x) {
        int i  = idx & 31;
        int hh = (idx >> 5) % nheads;
        int sr = (idx / (32*nheads)) % SQ;
        int b  =  idx / (32*nheads*SQ);
        size_t base = (((size_t)(b*SQ + sr))*nheads + hh)*HD + 2*i;
        float c = cs[sr*32 + i], s = sn[sr*32 + i];
        float xr = t[base], xi = t[base+1];
        t[base]   = xr*c - xi*s;
        t[base+1] = xr*s + xi*c;
    }
}

// ---------------- Tiled GEMM: C = epi(A@B) ----------------
// 64x64 tile, K-chunk 32, 256 threads, 4x4 micro-tile.
// EPI: 0=none, 1=+aux (residual), 2=silu, 3=*aux (elementwise)
template<int EPI>
__global__ void gemm_k(const float* __restrict__ A, const float* __restrict__ Bm,
                       const float* __restrict__ aux, float* __restrict__ C,
                       int M, int N, int K)
{
    __shared__ float As[32][68];   // As[k][m] (transposed for float4 reads)
    __shared__ float Bs[32][68];   // Bs[k][n]
    int tx = threadIdx.x & 15, ty = threadIdx.x >> 4;
    int m0 = blockIdx.y*64, n0 = blockIdx.x*64;
    float acc[4][4] = {};

    for (int k0 = 0; k0 < K; k0 += 32) {
        #pragma unroll
        for (int l = 0; l < 8; l++) {
            int e = threadIdx.x + l*256;
            int kk = e & 31, mm = e >> 5;
            As[kk][mm] = A[(size_t)(m0+mm)*K + k0 + kk];
        }
        #pragma unroll
        for (int l = 0; l < 8; l++) {
            int e = threadIdx.x + l*256;
            int nn = e & 63, kk = e >> 6;
            Bs[kk][nn] = Bm[(size_t)(k0+kk)*N + n0 + nn];
        }
        __syncthreads();
        #pragma unroll
        for (int kk = 0; kk < 32; kk++) {
            float4 a = *(const float4*)&As[kk][ty*4];
            float4 b = *(const float4*)&Bs[kk][tx*4];
            float av[4] = {a.x,a.y,a.z,a.w};
            float bv[4] = {b.x,b.y,b.z,b.w};
            #pragma unroll
            for (int i = 0; i < 4; i++)
                #pragma unroll
                for (int j = 0; j < 4; j++)
                    acc[i][j] += av[i]*bv[j];
        }
        __syncthreads();
    }

    #pragma unroll
    for (int i = 0; i < 4; i++)
        #pragma unroll
        for (int j = 0; j < 4; j++) {
            size_t idx = (size_t)(m0 + ty*4 + i)*N + n0 + tx*4 + j;
            float vv = acc[i][j];
            if (EPI == 1) vv += aux[idx];
            else if (EPI == 2) vv = vv / (1.f + __expf(-vv));
            else if (EPI == 3) vv *= aux[idx];
            C[idx] = vv;
        }
}

// ---------------- Flash attention (causal, GQA 4:1) ----------------
// Block: 64 queries x one (b,h). BLOCK_N = 32. 256 threads.
__global__ void attn_k(const float* __restrict__ q, const float* __restrict__ k,
                       const float* __restrict__ v, float* __restrict__ o)
{
    __shared__ float Qs[64][68];   // Qs[d][m]
    __shared__ float Ks[64][36];   // Ks[d][n]
    __shared__ float Vs[32][68];   // Vs[n][d]
    __shared__ float Ps[64][36];   // scores / probs [m][n]
    __shared__ float rmax[64], rsum[64], rcorr[64];

    int tid = threadIdx.x, tx = tid & 15, ty = tid >> 4;
    int bh = blockIdx.y;
    int b = bh >> 5, h = bh & 31;
    int kh = h >> 2;               // GQA: 32 heads -> 8 kv heads
    int q0 = blockIdx.x*64;

    #pragma unroll
    for (int l = 0; l < 16; l++) {
        int e = tid + l*256;
        int d = e & 63, m = e >> 6;
        Qs[d][m] = q[((size_t)(b*SQ + q0 + m)*NH + h)*HD + d];
    }
    if (tid < 64) { rmax[tid] = -1e30f; rsum[tid] = 0.f; }
    float oacc[4][4] = {};
    int ntiles = (q0 + 64) >> 5;   // causal: only kv tiles with k0 <= q0+63
    __syncthreads();

    for (int t = 0; t < ntiles; t++) {
        int k0 = t*32;
        #pragma unroll
        for (int l = 0; l < 8; l++) {
            int e = tid + l*256;
            int d = e & 63, n = e >> 6;
            size_t src = ((size_t)(b*SQ + k0 + n)*NKV + kh)*HD + d;
            Ks[d][n] = k[src];
            Vs[n][d] = v[src];
        }
        __syncthreads();

        // S = Q K^T * scale  (64m x 32n, each thread 4x2)
        float s2[4][2] = {};
        #pragma unroll
        for (int d = 0; d < 64; d++) {
            float4 a = *(const float4*)&Qs[d][ty*4];
            float2 bb = *(const float2*)&Ks[d][tx*2];
            float av[4] = {a.x,a.y,a.z,a.w};
            #pragma unroll
            for (int i = 0; i < 4; i++) {
                s2[i][0] += av[i]*bb.x;
                s2[i][1] += av[i]*bb.y;
            }
        }
        #pragma unroll
        for (int i = 0; i < 4; i++)
            #pragma unroll
            for (int j = 0; j < 2; j++) {
                int m = ty*4 + i, n = tx*2 + j;
                float sv = s2[i][j]*0.125f;
                if (k0 + n > q0 + m) sv = -1e30f;   // causal mask
                Ps[m][n] = sv;
            }
        __syncthreads();

        // Online softmax row pass (one thread per row)
        if (tid < 64) {
            int r = tid;
            float tm = -1e30f;
            for (int n = 0; n < 32; n++) tm = fmaxf(tm, Ps[r][n]);
            float nm = fmaxf(rmax[r], tm);
            float c  = __expf(rmax[r] - nm);
            float ps = 0.f;
            for (int n = 0; n < 32; n++) {
                float p = __expf(Ps[r][n] - nm);
                Ps[r][n] = p; ps += p;
            }
            rsum[r] = rsum[r]*c + ps;
            rmax[r] = nm;
            rcorr[r] = c;
        }
        __syncthreads();

        // Rescale O, then O += P @ V
        float cm[4];
        #pragma unroll
        for (int i = 0; i < 4; i++) cm[i] = rcorr[ty*4 + i];
        #pragma unroll
        for (int i = 0; i < 4; i++)
            #pragma unroll
            for (int j = 0; j < 4; j++) oacc[i][j] *= cm[i];
        #pragma unroll
        for (int n = 0; n < 32; n++) {
            float4 v4 = *(const float4*)&Vs[n][tx*4];
            float vv[4] = {v4.x,v4.y,v4.z,v4.w};
            #pragma unroll
            for (int i = 0; i < 4; i++) {
                float p = Ps[ty*4 + i][n];
                #pragma unroll
                for (int j = 0; j < 4; j++) oacc[i][j] += p*vv[j];
            }
        }
        __syncthreads();
    }

    #pragma unroll
    for (int i = 0; i < 4; i++) {
        float inv = 1.f / rsum[ty*4 + i];
        #pragma unroll
        for (int j = 0; j < 4; j++) {
            int m = ty*4 + i, dd = tx*4 + j;
            o[((size_t)(b*SQ + q0 + m)*NH + h)*HD + dd] = oacc[i][j]*inv;
        }
    }
}

// ---------------- launch ----------------
extern "C" void kernel_launch(void* const* d_in, const int* in_sizes, int n_in,
                              void* d_out, int out_size)
{
    const float* x   = (const float*)d_in[0];
    const float* wq  = (const float*)d_in[1];
    const float* wk  = (const float*)d_in[2];
    const float* wv  = (const float*)d_in[3];
    const float* wo  = (const float*)d_in[4];
    const float* w1  = (const float*)d_in[5];
    const float* w2  = (const float*)d_in[6];
    const float* w3  = (const float*)d_in[7];
    const float* anw = (const float*)d_in[8];
    const float* fnw = (const float*)d_in[9];
    const float* fc  = (const float*)d_in[10];
    const float* fs  = (const float*)d_in[11];
    float* out = (float*)d_out;
    (void)in_sizes; (void)n_in; (void)out_size;

    float *h, *q, *k, *v, *attn, *x2, *h2, *f1, *f2;
    cudaGetSymbolAddress((void**)&h,    g_h);
    cudaGetSymbolAddress((void**)&q,    g_q);
    cudaGetSymbolAddress((void**)&k,    g_k);
    cudaGetSymbolAddress((void**)&v,    g_v);
    cudaGetSymbolAddress((void**)&attn, g_attn);
    cudaGetSymbolAddress((void**)&x2,   g_x2);
    cudaGetSymbolAddress((void**)&h2,   g_h2);
    cudaGetSymbolAddress((void**)&f1,   g_f1);
    cudaGetSymbolAddress((void**)&f2,   g_f2);

    // 1. h = rmsnorm(x) * attn_norm_w
    rmsnorm_k<<<ROWS, 256>>>(x, anw, h);
    // 2. q/k/v projections
    gemm_k<0><<<dim3(NH*HD/64,  ROWS/64), 256>>>(h, wq, nullptr, q, ROWS, NH*HD,  DD);
    gemm_k<0><<<dim3(NKV*HD/64, ROWS/64), 256>>>(h, wk, nullptr, k, ROWS, NKV*HD, DD);
    gemm_k<0><<<dim3(NKV*HD/64, ROWS/64), 256>>>(h, wv, nullptr, v, ROWS, NKV*HD, DD);
    // 3. RoPE
    rope_k<<<2048, 256>>>(q, fc, fs, NH,  ROWS*NH*32);
    rope_k<<<512,  256>>>(k, fc, fs, NKV, ROWS*NKV*32);
    // 4. attention
    attn_k<<<dim3(SQ/64, BB*NH), 256>>>(q, k, v, attn);
    // 5. x2 = x + attn @ wo
    gemm_k<1><<<dim3(DD/64, ROWS/64), 256>>>(attn, wo, x, x2, ROWS, DD, NH*HD);
    // 6. h2 = rmsnorm(x2) * ffn_norm_w
    rmsnorm_k<<<ROWS, 256>>>(x2, fnw, h2);
    // 7. f1 = silu(h2 @ w1); f2 = f1 * (h2 @ w3)
    gemm_k<2><<<dim3(FF/64, ROWS/64), 256>>>(h2, w1, nullptr, f1, ROWS, FF, DD);
    gemm_k<3><<<dim3(FF/64, ROWS/64), 256>>>(h2, w3, f1,      f2, ROWS, FF, DD);
    // 8. out = x2 + f2 @ w2
    gemm_k<1><<<dim3(DD/64, ROWS/64), 256>>>(f2, w2, x2, out, ROWS, DD, FF);
}

// round 4
// speedup vs baseline: 3.0499x; 3.0499x over previous
#include <cuda_runtime.h>
#include <math.h>
#include <stdint.h>

// Problem constants
#define BB   2
#define SQ   1024
#define DD   2048
#define NH   32
#define NKV  8
#define HD   64
#define FF   5632
#define ROWS (BB*SQ)   // 2048

// Scratch (device globals: allocation-free)
__device__ float g_h   [ROWS*DD];
__device__ float g_q   [ROWS*NH*HD];
__device__ float g_k   [ROWS*NKV*HD];
__device__ float g_v   [ROWS*NKV*HD];
__device__ float g_attn[ROWS*NH*HD];
__device__ float g_x2  [ROWS*DD];
__device__ float g_h2  [ROWS*DD];
__device__ float g_f1  [ROWS*FF];
__device__ float g_f2  [ROWS*FF];

// ---------------- RMSNorm: one block per row ----------------
__global__ void rmsnorm_k(const float* __restrict__ x, const float* __restrict__ w,
                          float* __restrict__ out)
{
    int row = blockIdx.x;
    const float* xr = x + (size_t)row*DD;
    float* orow = out + (size_t)row*DD;
    float ss = 0.f;
    for (int i = threadIdx.x; i < DD; i += 256) { float v = xr[i]; ss += v*v; }
    __shared__ float red[256];
    red[threadIdx.x] = ss; __syncthreads();
    for (int s = 128; s > 0; s >>= 1) {
        if (threadIdx.x < s) red[threadIdx.x] += red[threadIdx.x+s];
        __syncthreads();
    }
    float inv = rsqrtf(red[0]/(float)DD + 1e-5f);
    for (int i = threadIdx.x; i < DD; i += 256) orow[i] = xr[i]*inv*w[i];
}

// ---------------- RoPE (in place) ----------------
__global__ void rope_k(float* __restrict__ t, const float* __restrict__ cs,
                       const float* __restrict__ sn, int nheads, int total)
{
    for (int idx = blockIdx.x*blockDim.x + threadIdx.x; idx < total;
         idx += gridDim.x*blockDim.x) {
        int i  = idx & 31;
        int hh = (idx >> 5) % nheads;
        int sr = (idx / (32*nheads)) % SQ;
        int b  =  idx / (32*nheads*SQ);
        size_t base = (((size_t)(b*SQ + sr))*nheads + hh)*HD + 2*i;
        float c = cs[sr*32 + i], s = sn[sr*32 + i];
        float xr = t[base], xi = t[base+1];
        t[base]   = xr*c - xi*s;
        t[base+1] = xr*s + xi*c;
    }
}

// ---------------- TF32 tensor-core GEMM: C = epi(A@B) ----------------
// A[M,K] row-major, B[K,N] row-major. 128x128x32 tiles, 256 threads.
// Warp layout 2x4 (warp tile 64x32). mma.sync.m16n8k8.tf32.
// EPI: 0=none, 1=+aux, 2=silu, 3=*aux
__device__ __forceinline__ uint32_t f2tf32(float f) {
    uint32_t u;
    asm("cvt.rna.tf32.f32 %0, %1;" : "=r"(u) : "f"(f));
    return u;
}

template<int EPI>
__global__ void __launch_bounds__(256, 2)
gemm_tf32(const float* __restrict__ A, const float* __restrict__ Bm,
          const float* __restrict__ aux, float* __restrict__ C,
          int M, int N, int K)
{
    __shared__ uint32_t As[128][36];   // [m][k], stride 36
    __shared__ uint32_t Bs[32][136];   // [k][n], stride 136

    int tid  = threadIdx.x;
    int wid  = tid >> 5, lane = tid & 31;
    int lr   = lane >> 2, lc = lane & 3;
    int wm   = (wid & 1) * 64;
    int wn   = (wid >> 1) * 32;
    int m0   = blockIdx.y * 128, n0 = blockIdx.x * 128;

    float acc[4][4][4] = {};   // [mtile][ntile][c0..c3]

    // global load mapping
    int am = tid >> 3;            // + p*32, p=0..3
    int ak = (tid & 7) * 4;
    int bk = tid >> 5;            // + p*8,  p=0..3
    int bn = (tid & 31) * 4;

    for (int k0 = 0; k0 < K; k0 += 32) {
        #pragma unroll
        for (int p = 0; p < 4; p++) {
            float4 v = *(const float4*)&A[(size_t)(m0 + am + p*32)*K + k0 + ak];
            *(uint4*)&As[am + p*32][ak] =
                make_uint4(f2tf32(v.x), f2tf32(v.y), f2tf32(v.z), f2tf32(v.w));
        }
        #pragma unroll
        for (int p = 0; p < 4; p++) {
            float4 v = *(const float4*)&Bm[(size_t)(k0 + bk + p*8)*N + n0 + bn];
            *(uint4*)&Bs[bk + p*8][bn] =
                make_uint4(f2tf32(v.x), f2tf32(v.y), f2tf32(v.z), f2tf32(v.w));
        }
        __syncthreads();

        #pragma unroll
        for (int ks = 0; ks < 4; ks++) {
            uint32_t af[4][4], bf[4][2];
            int kk = ks*8 + lc;
            #pragma unroll
            for (int i = 0; i < 4; i++) {
                int m = wm + i*16 + lr;
                af[i][0] = As[m    ][kk    ];
                af[i][1] = As[m + 8][kk    ];
                af[i][2] = As[m    ][kk + 4];
                af[i][3] = As[m + 8][kk + 4];
            }
            #pragma unroll
            for (int j = 0; j < 4; j++) {
                int n = wn + j*8 + lr;
                bf[j][0] = Bs[kk    ][n];
                bf[j][1] = Bs[kk + 4][n];
            }
            #pragma unroll
            for (int i = 0; i < 4; i++)
                #pragma unroll
                for (int j = 0; j < 4; j++) {
                    asm volatile(
                        "mma.sync.aligned.m16n8k8.row.col.f32.tf32.tf32.f32 "
                        "{%0,%1,%2,%3}, {%4,%5,%6,%7}, {%8,%9}, {%0,%1,%2,%3};"
                        : "+f"(acc[i][j][0]), "+f"(acc[i][j][1]),
                          "+f"(acc[i][j][2]), "+f"(acc[i][j][3])
                        : "r"(af[i][0]), "r"(af[i][1]), "r"(af[i][2]), "r"(af[i][3]),
                          "r"(bf[j][0]), "r"(bf[j][1]));
                }
        }
        __syncthreads();
    }

    // epilogue: c0,c1 at (m, n), (m, n+1); c2,c3 at (m+8, n), (m+8, n+1)
    #pragma unroll
    for (int i = 0; i < 4; i++) {
        #pragma unroll
        for (int j = 0; j < 4; j++) {
            int m = m0 + wm + i*16 + lr;
            int n = n0 + wn + j*8 + 2*lc;
            #pragma unroll
            for (int half = 0; half < 2; half++) {
                size_t idx = (size_t)(m + half*8)*N + n;
                float v0 = acc[i][j][half*2], v1 = acc[i][j][half*2 + 1];
                if (EPI == 1)      { v0 += aux[idx];   v1 += aux[idx+1]; }
                else if (EPI == 2) { v0 = v0/(1.f + __expf(-v0));
                                     v1 = v1/(1.f + __expf(-v1)); }
                else if (EPI == 3) { v0 *= aux[idx];   v1 *= aux[idx+1]; }
                *(float2*)&C[idx] = make_float2(v0, v1);
            }
        }
    }
}

// ---------------- Flash attention (causal, GQA 4:1), fp32 ----------------
__global__ void attn_k(const float* __restrict__ q, const float* __restrict__ k,
                       const float* __restrict__ v, float* __restrict__ o)
{
    __shared__ float Qs[64][68];   // Qs[d][m]
    __shared__ float Ks[64][36];   // Ks[d][n]
    __shared__ float Vs[32][68];   // Vs[n][d]
    __shared__ float Ps[64][36];   // scores / probs [m][n]
    __shared__ float rmax[64], rsum[64], rcorr[64];

    int tid = threadIdx.x, tx = tid & 15, ty = tid >> 4;
    int bh = blockIdx.y;
    int b = bh >> 5, h = bh & 31;
    int kh = h >> 2;
    int q0 = blockIdx.x*64;

    #pragma unroll
    for (int l = 0; l < 16; l++) {
        int e = tid + l*256;
        int d = e & 63, m = e >> 6;
        Qs[d][m] = q[((size_t)(b*SQ + q0 + m)*NH + h)*HD + d];
    }
    if (tid < 64) { rmax[tid] = -1e30f; rsum[tid] = 0.f; }
    float oacc[4][4] = {};
    int ntiles = (q0 + 64) >> 5;
    __syncthreads();

    for (int t = 0; t < ntiles; t++) {
        int k0 = t*32;
        #pragma unroll
        for (int l = 0; l < 8; l++) {
            int e = tid + l*256;
            int d = e & 63, n = e >> 6;
            size_t src = ((size_t)(b*SQ + k0 + n)*NKV + kh)*HD + d;
            Ks[d][n] = k[src];
            Vs[n][d] = v[src];
        }
        __syncthreads();

        float s2[4][2] = {};
        #pragma unroll
        for (int d = 0; d < 64; d++) {
            float4 a = *(const float4*)&Qs[d][ty*4];
            float2 bb = *(const float2*)&Ks[d][tx*2];
            float av[4] = {a.x,a.y,a.z,a.w};
            #pragma unroll
            for (int i = 0; i < 4; i++) {
                s2[i][0] += av[i]*bb.x;
                s2[i][1] += av[i]*bb.y;
            }
        }
        #pragma unroll
        for (int i = 0; i < 4; i++)
            #pragma unroll
            for (int j = 0; j < 2; j++) {
                int m = ty*4 + i, n = tx*2 + j;
                float sv = s2[i][j]*0.125f;
                if (k0 + n > q0 + m) sv = -1e30f;
                Ps[m][n] = sv;
            }
        __syncthreads();

        if (tid < 64) {
            int r = tid;
            float tm = -1e30f;
            for (int n = 0; n < 32; n++) tm = fmaxf(tm, Ps[r][n]);
            float nm = fmaxf(rmax[r], tm);
            float c  = __expf(rmax[r] - nm);
            float ps = 0.f;
            for (int n = 0; n < 32; n++) {
                float p = __expf(Ps[r][n] - nm);
                Ps[r][n] = p; ps += p;
            }
            rsum[r] = rsum[r]*c + ps;
            rmax[r] = nm;
            rcorr[r] = c;
        }
        __syncthreads();

        float cm[4];
        #pragma unroll
        for (int i = 0; i < 4; i++) cm[i] = rcorr[ty*4 + i];
        #pragma unroll
        for (int i = 0; i < 4; i++)
            #pragma unroll
            for (int j = 0; j < 4; j++) oacc[i][j] *= cm[i];
        #pragma unroll
        for (int n = 0; n < 32; n++) {
            float4 v4 = *(const float4*)&Vs[n][tx*4];
            float vv[4] = {v4.x,v4.y,v4.z,v4.w};
            #pragma unroll
            for (int i = 0; i < 4; i++) {
                float p = Ps[ty*4 + i][n];
                #pragma unroll
                for (int j = 0; j < 4; j++) oacc[i][j] += p*vv[j];
            }
        }
        __syncthreads();
    }

    #pragma unroll
    for (int i = 0; i < 4; i++) {
        float inv = 1.f / rsum[ty*4 + i];
        #pragma unroll
        for (int j = 0; j < 4; j++) {
            int m = ty*4 + i, dd = tx*4 + j;
            o[((size_t)(b*SQ + q0 + m)*NH + h)*HD + dd] = oacc[i][j]*inv;
        }
    }
}

// ---------------- launch ----------------
extern "C" void kernel_launch(void* const* d_in, const int* in_sizes, int n_in,
                              void* d_out, int out_size)
{
    const float* x   = (const float*)d_in[0];
    const float* wq  = (const float*)d_in[1];
    const float* wk  = (const float*)d_in[2];
    const float* wv  = (const float*)d_in[3];
    const float* wo  = (const float*)d_in[4];
    const float* w1  = (const float*)d_in[5];
    const float* w2  = (const float*)d_in[6];
    const float* w3  = (const float*)d_in[7];
    const float* anw = (const float*)d_in[8];
    const float* fnw = (const float*)d_in[9];
    const float* fc  = (const float*)d_in[10];
    const float* fs  = (const float*)d_in[11];
    float* out = (float*)d_out;
    (void)in_sizes; (void)n_in; (void)out_size;

    float *h, *q, *k, *v, *attn, *x2, *h2, *f1, *f2;
    cudaGetSymbolAddress((void**)&h,    g_h);
    cudaGetSymbolAddress((void**)&q,    g_q);
    cudaGetSymbolAddress((void**)&k,    g_k);
    cudaGetSymbolAddress((void**)&v,    g_v);
    cudaGetSymbolAddress((void**)&attn, g_attn);
    cudaGetSymbolAddress((void**)&x2,   g_x2);
    cudaGetSymbolAddress((void**)&h2,   g_h2);
    cudaGetSymbolAddress((void**)&f1,   g_f1);
    cudaGetSymbolAddress((void**)&f2,   g_f2);

    // 1. h = rmsnorm(x) * attn_norm_w
    rmsnorm_k<<<ROWS, 256>>>(x, anw, h);
    // 2. q/k/v projections (TF32 tensor cores)
    gemm_tf32<0><<<dim3(NH*HD/128,  ROWS/128), 256>>>(h, wq, nullptr, q, ROWS, NH*HD,  DD);
    gemm_tf32<0><<<dim3(NKV*HD/128, ROWS/128), 256>>>(h, wk, nullptr, k, ROWS, NKV*HD, DD);
    gemm_tf32<0><<<dim3(NKV*HD/128, ROWS/128), 256>>>(h, wv, nullptr, v, ROWS, NKV*HD, DD);
    // 3. RoPE
    rope_k<<<2048, 256>>>(q, fc, fs, NH,  ROWS*NH*32);
    rope_k<<<512,  256>>>(k, fc, fs, NKV, ROWS*NKV*32);
    // 4. attention (fp32)
    attn_k<<<dim3(SQ/64, BB*NH), 256>>>(q, k, v, attn);
    // 5. x2 = x + attn @ wo
    gemm_tf32<1><<<dim3(DD/128, ROWS/128), 256>>>(attn, wo, x, x2, ROWS, DD, NH*HD);
    // 6. h2 = rmsnorm(x2) * ffn_norm_w
    rmsnorm_k<<<ROWS, 256>>>(x2, fnw, h2);
    // 7. f1 = silu(h2 @ w1); f2 = f1 * (h2 @ w3)
    gemm_tf32<2><<<dim3(FF/128, ROWS/128), 256>>>(h2, w1, nullptr, f1, ROWS, FF, DD);
    gemm_tf32<3><<<dim3(FF/128, ROWS/128), 256>>>(h2, w3, f1,      f2, ROWS, FF, DD);
    // 8. out = x2 + f2 @ w2
    gemm_tf32<1><<<dim3(DD/128, ROWS/128), 256>>>(f2, w2, x2, out, ROWS, DD, FF);
}